// round 5
// baseline (speedup 1.0000x reference)
#include <cuda_runtime.h>
#include <cuda_bf16.h>
#include <cstdint>

// ---------------------------------------------------------------------------
// ProtoPNet fused kernel, GB300 sm_103a
//   features   [64,128,14,14] f32   d_in[0]
//   prototypes [2000,128,1,1] f32   d_in[1]
//   last_weight[200,2000]     f32   d_in[2]
//   out: logits [64,200] then min_dist [64,2000]  (140800 f32)
//
// sim = log((d+1)/(d+eps)) is strictly decreasing in d, relu is monotone:
//   max_hw sim == sim(relu(min_hw d_raw)),  min_hw relu(d) == relu(min_hw d_raw)
// so we only need min_hw(x_sq - 2*xp) per (n,p).
// Main GEMM uses Blackwell packed fp32 FFMA2 via PTX fma.rn.f32x2.
// ---------------------------------------------------------------------------

typedef unsigned long long ull;

#define NB   64       // batch
#define DD   128      // feature dim (K)
#define HW   196      // 14*14
#define HWP  256      // padded hw (128 f32x2 pairs)
#define NPAIR_VALID 98   // 196/2 valid pairs
#define NP   2000     // prototypes
#define TP   64       // prototypes per CTA
#define PT_TILES 32   // ceil(2000/64)
#define EPSV 1e-4f

#define XSQ_STRIDE 200   // pad 196 -> 200 so float2 loads stay 8B aligned

__device__ float g_psq[NP];
__device__ float g_xsq[NB * XSQ_STRIDE];
__device__ float g_sim[NB * NP];

// ---- packed f32x2 helpers (Blackwell) -------------------------------------
__device__ __forceinline__ ull splat2(float v) {
    ull r;
    asm("mov.b64 %0, {%1, %1};" : "=l"(r) : "f"(v));
    return r;
}
__device__ __forceinline__ void fma2(ull& d, ull a, ull b) {
    asm("fma.rn.f32x2 %0, %1, %2, %3;" : "=l"(d) : "l"(a), "l"(b), "l"(d));
}
__device__ __forceinline__ float2 unpack2(ull v) {
    float2 r;
    asm("mov.b64 {%0, %1}, %2;" : "=f"(r.x), "=f"(r.y) : "l"(v));
    return r;
}

// ---- x_sq[n][hw] = sum_d f^2 ----------------------------------------------
__global__ void xsq_kernel(const float* __restrict__ F) {
    int n  = blockIdx.x;
    int hw = threadIdx.x;
    if (hw < HW) {
        const float* base = F + (size_t)n * DD * HW + hw;
        float s = 0.f;
#pragma unroll 8
        for (int k = 0; k < DD; k++) {
            float v = base[(size_t)k * HW];
            s = fmaf(v, v, s);
        }
        g_xsq[n * XSQ_STRIDE + hw] = s;
    }
}

// ---- p_sq[p] = sum_d p^2 (one warp per prototype) -------------------------
__global__ void psq_kernel(const float* __restrict__ P) {
    int w    = (blockIdx.x * blockDim.x + threadIdx.x) >> 5;
    int lane = threadIdx.x & 31;
    if (w < NP) {
        const float* row = P + (size_t)w * DD;
        float s = 0.f;
#pragma unroll
        for (int i = 0; i < 4; i++) {
            float v = row[lane + 32 * i];
            s = fmaf(v, v, s);
        }
#pragma unroll
        for (int off = 16; off; off >>= 1)
            s += __shfl_xor_sync(0xffffffffu, s, off);
        if (lane == 0) g_psq[w] = s;
    }
}

// ---- main fused GEMM + hw-min reduction -----------------------------------
// grid (PT_TILES, NB), 256 threads.
// smem: feat [128][256] f32 (131072 B) + proto [64][128] f32 (32768 B) = 163840 B
#define SMEM_BYTES ((DD * HWP + TP * DD) * 4)

__global__ __launch_bounds__(256, 1)
void proto_main_kernel(const float* __restrict__ F,
                       const float* __restrict__ P,
                       float* __restrict__ out_mind) {
    extern __shared__ float sm[];
    float* sf = sm;                // feat  [128][256]
    float* sp = sm + DD * HWP;     // proto [64][128]

    const int tid = threadIdx.x;
    const int tx  = tid & 31;      // lane -> hw-pair base
    const int ty  = tid >> 5;      // warp -> proto group (8 protos)
    const int n   = blockIdx.y;
    const int p0  = blockIdx.x * TP;

    // stage features (coalesced) + zero-pad hw 196..255
    const float* Fn = F + (size_t)n * DD * HW;
    for (int idx = tid; idx < DD * HW; idx += 256) {
        int k  = idx / HW;
        int hw = idx - k * HW;
        sf[k * HWP + hw] = Fn[idx];
    }
    for (int idx = tid; idx < DD * (HWP - HW); idx += 256) {
        int k  = idx / (HWP - HW);
        int hw = HW + (idx - k * (HWP - HW));
        sf[k * HWP + hw] = 0.f;
    }
    // stage prototypes (coalesced), zero beyond NP
    for (int idx = tid; idx < TP * DD; idx += 256) {
        int pl = idx >> 7;   // /128
        int k  = idx & 127;
        int gp = p0 + pl;
        sp[idx] = (gp < NP) ? P[(size_t)gp * DD + k] : 0.f;
    }
    __syncthreads();

    // accumulators: 8 protos x 4 hw-pairs, f32x2 each
    ull acc[8][4];
#pragma unroll
    for (int i = 0; i < 8; i++)
#pragma unroll
        for (int j = 0; j < 4; j++) acc[i][j] = 0ull;

    const ull*   f2  = reinterpret_cast<const ull*>(sf);   // [128][128] pairs
    const float* myp = sp + (ty * 8) * DD;

#pragma unroll 2
    for (int k = 0; k < DD; k += 2) {
        ull fa[4], fb[4];
#pragma unroll
        for (int j = 0; j < 4; j++) {
            fa[j] = f2[(k    ) * (HWP / 2) + tx + 32 * j];
            fb[j] = f2[(k + 1) * (HWP / 2) + tx + 32 * j];
        }
#pragma unroll
        for (int i = 0; i < 8; i++) {
            float2 pv = *reinterpret_cast<const float2*>(myp + i * DD + k);
            ull b0 = splat2(pv.x);
            ull b1 = splat2(pv.y);
#pragma unroll
            for (int j = 0; j < 4; j++) fma2(acc[i][j], fa[j], b0);
#pragma unroll
            for (int j = 0; j < 4; j++) fma2(acc[i][j], fb[j], b1);
        }
    }

    // epilogue: min over hw of (x_sq - 2*xp); add p_sq; relu; sim = log(...)
    const float2* xq = reinterpret_cast<const float2*>(g_xsq + n * XSQ_STRIDE);
    float2 xs[4];
#pragma unroll
    for (int j = 0; j < 4; j++) {
        int pi = tx + 32 * j;
        if (pi < NPAIR_VALID) xs[j] = xq[pi];
    }

#pragma unroll
    for (int i = 0; i < 8; i++) {
        float m = 3.4028235e38f;
#pragma unroll
        for (int j = 0; j < 4; j++) {
            int pi = tx + 32 * j;
            if (pi < NPAIR_VALID) {
                float2 a = unpack2(acc[i][j]);
                m = fminf(m, fmaf(-2.f, a.x, xs[j].x));
                m = fminf(m, fmaf(-2.f, a.y, xs[j].y));
            }
        }
#pragma unroll
        for (int off = 16; off; off >>= 1)
            m = fminf(m, __shfl_xor_sync(0xffffffffu, m, off));
        if (tx == 0) {
            int p = p0 + ty * 8 + i;
            if (p < NP) {
                float md = fmaxf(m + g_psq[p], 0.f);
                out_mind[n * NP + p] = md;
                g_sim[n * NP + p]    = logf((md + 1.0f) / (md + EPSV));
            }
        }
    }
}

// ---- logits[n][c] = sum_p sim[n][p] * W[c][p] -----------------------------
__global__ void logits_kernel(const float* __restrict__ W,
                              float* __restrict__ out_logits) {
    __shared__ float s[NP];
    const int n   = blockIdx.x;
    const int tid = threadIdx.x;
    for (int i = tid; i < NP; i += 256) s[i] = g_sim[n * NP + i];
    __syncthreads();

    const int w    = tid >> 5;
    const int lane = tid & 31;
    for (int c = w; c < 200; c += 8) {
        const float* wr = W + (size_t)c * NP;
        float a = 0.f;
        for (int p = lane; p < NP; p += 32) a = fmaf(s[p], wr[p], a);
#pragma unroll
        for (int off = 16; off; off >>= 1)
            a += __shfl_xor_sync(0xffffffffu, a, off);
        if (lane == 0) out_logits[n * 200 + c] = a;
    }
}

// ---------------------------------------------------------------------------
extern "C" void kernel_launch(void* const* d_in, const int* in_sizes, int n_in,
                              void* d_out, int out_size) {
    const float* F = (const float*)d_in[0];  // features
    const float* P = (const float*)d_in[1];  // prototypes
    const float* W = (const float*)d_in[2];  // last_weight

    float* logits = (float*)d_out;           // [64,200]
    float* mind   = logits + NB * 200;       // [64,2000]

    // idempotent, non-stream host API: capture-safe, called every time
    cudaFuncSetAttribute(proto_main_kernel,
                         cudaFuncAttributeMaxDynamicSharedMemorySize,
                         SMEM_BYTES);

    xsq_kernel<<<NB, 256>>>(F);
    psq_kernel<<<(NP + 7) / 8, 256>>>(P);    // 8 warps/CTA, 1 warp per proto
    proto_main_kernel<<<dim3(PT_TILES, NB), 256, SMEM_BYTES>>>(F, P, mind);
    logits_kernel<<<NB, 256>>>(W, logits);
}

// round 7
// speedup vs baseline: 1.5212x; 1.5212x over previous
#include <cuda_runtime.h>
#include <cuda_bf16.h>
#include <cstdint>

// ---------------------------------------------------------------------------
// ProtoPNet fused kernel, GB300 sm_103a  (Round 6 = Round 5 re-bench, infra flake)
//   features   [64,128,14,14] f32   d_in[0]
//   prototypes [2000,128,1,1] f32   d_in[1]
//   last_weight[200,2000]     f32   d_in[2]
//   out: logits [64,200] then min_dist [64,2000]  (140800 f32)
//
// sim = log((d+1)/(d+eps)) strictly decreasing, relu monotone =>
// only min_hw(x_sq - 2*xp) per (n,p) is needed; one log per (n,p).
// Main GEMM: Blackwell packed fp32 FFMA2 (fma.rn.f32x2), 512 thr, 128 protos/CTA.
// Logits: tiled L2-resident GEMM, 200 CTAs.
// ---------------------------------------------------------------------------

typedef unsigned long long ull;

#define NB   64       // batch
#define DD   128      // feature dim (K)
#define HW   196      // 14*14
#define HWP  256      // padded hw (128 f32x2 pairs)
#define NPAIR_VALID 98
#define NP   2000     // prototypes
#define TP   128      // prototypes per CTA
#define PT_TILES 16   // ceil(2000/128)
#define EPSV 1e-4f
#define NC   200      // classes

#define XSQ_STRIDE 200   // pad 196 -> 200 (8B-aligned float2)

__device__ float g_psq[NP];
__device__ float g_xsq[NB * XSQ_STRIDE];
__device__ float g_sim[NB * NP];

// ---- packed f32x2 helpers (Blackwell) -------------------------------------
__device__ __forceinline__ ull splat2(float v) {
    ull r;
    asm("mov.b64 %0, {%1, %1};" : "=l"(r) : "f"(v));
    return r;
}
__device__ __forceinline__ void fma2(ull& d, ull a, ull b) {
    asm("fma.rn.f32x2 %0, %1, %2, %3;" : "=l"(d) : "l"(a), "l"(b), "l"(d));
}
__device__ __forceinline__ float2 unpack2(ull v) {
    float2 r;
    asm("mov.b64 {%0, %1}, %2;" : "=f"(r.x), "=f"(r.y) : "l"(v));
    return r;
}

// ---- x_sq[n][hw] ----------------------------------------------------------
__global__ void xsq_kernel(const float* __restrict__ F) {
    int n  = blockIdx.x;
    int hw = threadIdx.x;
    if (hw < HW) {
        const float* base = F + (size_t)n * DD * HW + hw;
        float s = 0.f;
#pragma unroll 8
        for (int k = 0; k < DD; k++) {
            float v = base[(size_t)k * HW];
            s = fmaf(v, v, s);
        }
        g_xsq[n * XSQ_STRIDE + hw] = s;
    }
}

// ---- p_sq[p] (one warp per prototype) -------------------------------------
__global__ void psq_kernel(const float* __restrict__ P) {
    int w    = (blockIdx.x * blockDim.x + threadIdx.x) >> 5;
    int lane = threadIdx.x & 31;
    if (w < NP) {
        const float* row = P + (size_t)w * DD;
        float s = 0.f;
#pragma unroll
        for (int i = 0; i < 4; i++) {
            float v = row[lane + 32 * i];
            s = fmaf(v, v, s);
        }
#pragma unroll
        for (int off = 16; off; off >>= 1)
            s += __shfl_xor_sync(0xffffffffu, s, off);
        if (lane == 0) g_psq[w] = s;
    }
}

// ---- main fused GEMM + hw-min ---------------------------------------------
// grid (PT_TILES, NB), 512 threads (16 warps, 8 protos/warp).
// smem: feat [128][256] (131072 B) + proto [128][128] (65536 B) = 196608 B
#define SMEM_MAIN ((DD * HWP + TP * DD) * 4)

__global__ __launch_bounds__(512, 1)
void proto_main_kernel(const float* __restrict__ F,
                       const float* __restrict__ P,
                       float* __restrict__ out_mind) {
    extern __shared__ float sm[];
    float* sf = sm;                // feat  [128][256]
    float* sp = sm + DD * HWP;     // proto [128][128]

    const int tid = threadIdx.x;
    const int tx  = tid & 31;      // lane -> hw-pair base
    const int ty  = tid >> 5;      // warp -> proto group (8 protos), 0..15
    const int n   = blockIdx.y;
    const int p0  = blockIdx.x * TP;

    // stage features (coalesced) + zero-pad hw 196..255
    const float* Fn = F + (size_t)n * DD * HW;
    for (int idx = tid; idx < DD * HW; idx += 512) {
        int k  = idx / HW;
        int hw = idx - k * HW;
        sf[k * HWP + hw] = Fn[idx];
    }
    for (int idx = tid; idx < DD * (HWP - HW); idx += 512) {
        int k  = idx / (HWP - HW);
        int hw = HW + (idx - k * (HWP - HW));
        sf[k * HWP + hw] = 0.f;
    }
    // stage prototypes, zero beyond NP
    for (int idx = tid; idx < TP * DD; idx += 512) {
        int pl = idx >> 7;
        int k  = idx & 127;
        int gp = p0 + pl;
        sp[idx] = (gp < NP) ? P[(size_t)gp * DD + k] : 0.f;
    }
    __syncthreads();

    ull acc[8][4];
#pragma unroll
    for (int i = 0; i < 8; i++)
#pragma unroll
        for (int j = 0; j < 4; j++) acc[i][j] = 0ull;

    const ull*   f2  = reinterpret_cast<const ull*>(sf);   // [128][128] pairs
    const float* myp = sp + (ty * 8) * DD;

#pragma unroll 2
    for (int k = 0; k < DD; k += 2) {
        ull fa[4], fb[4];
#pragma unroll
        for (int j = 0; j < 4; j++) {
            fa[j] = f2[(k    ) * (HWP / 2) + tx + 32 * j];
            fb[j] = f2[(k + 1) * (HWP / 2) + tx + 32 * j];
        }
#pragma unroll
        for (int i = 0; i < 8; i++) {
            float2 pv = *reinterpret_cast<const float2*>(myp + i * DD + k);
            ull b0 = splat2(pv.x);
            ull b1 = splat2(pv.y);
#pragma unroll
            for (int j = 0; j < 4; j++) fma2(acc[i][j], fa[j], b0);
#pragma unroll
            for (int j = 0; j < 4; j++) fma2(acc[i][j], fb[j], b1);
        }
    }

    // epilogue: min_hw(x_sq - 2*xp) + p_sq, relu, one log
    const float2* xq = reinterpret_cast<const float2*>(g_xsq + n * XSQ_STRIDE);
    float2 xs[4];
#pragma unroll
    for (int j = 0; j < 4; j++) {
        int pi = tx + 32 * j;
        if (pi < NPAIR_VALID) xs[j] = xq[pi];
    }

#pragma unroll
    for (int i = 0; i < 8; i++) {
        float m = 3.4028235e38f;
#pragma unroll
        for (int j = 0; j < 4; j++) {
            int pi = tx + 32 * j;
            if (pi < NPAIR_VALID) {
                float2 a = unpack2(acc[i][j]);
                m = fminf(m, fmaf(-2.f, a.x, xs[j].x));
                m = fminf(m, fmaf(-2.f, a.y, xs[j].y));
            }
        }
#pragma unroll
        for (int off = 16; off; off >>= 1)
            m = fminf(m, __shfl_xor_sync(0xffffffffu, m, off));
        if (tx == 0) {
            int p = p0 + ty * 8 + i;
            if (p < NP) {
                float md = fmaxf(m + g_psq[p], 0.f);
                out_mind[n * NP + p] = md;
                g_sim[n * NP + p]    = logf((md + 1.0f) / (md + EPSV));
            }
        }
    }
}

// ---- logits: tiled GEMM  logits[n][c] = sum_p sim[n][p] * W[c][p] ---------
// grid (25 c-tiles, 8 n-tiles), 256 threads (8 warps = 8 classes/CTA).
// smem: sim [8 n][2000] f32 = 64000 B (dynamic)
#define SMEM_LOGITS (8 * NP * 4)

__global__ __launch_bounds__(256, 1)
void logits_kernel(const float* __restrict__ W,
                   float* __restrict__ out_logits) {
    extern __shared__ float s[];           // [8][2000]
    const int tid  = threadIdx.x;
    const int lane = tid & 31;
    const int w    = tid >> 5;             // warp -> class within tile
    const int c    = blockIdx.x * 8 + w;
    const int n0   = blockIdx.y * 8;

    for (int idx = tid; idx < 8 * NP; idx += 256) {
        int ni = idx / NP;
        int p  = idx - ni * NP;
        s[idx] = g_sim[(n0 + ni) * NP + p];
    }
    __syncthreads();

    const float2* wr = reinterpret_cast<const float2*>(W + (size_t)c * NP);
    const float2* s0 = reinterpret_cast<const float2*>(s);   // [8][1000] pairs
    float2 acc[8];
#pragma unroll
    for (int i = 0; i < 8; i++) acc[i] = make_float2(0.f, 0.f);

    for (int j = lane; j < NP / 2; j += 32) {
        float2 wv = wr[j];
#pragma unroll
        for (int i = 0; i < 8; i++) {
            float2 sv = s0[i * (NP / 2) + j];
            acc[i].x = fmaf(wv.x, sv.x, acc[i].x);
            acc[i].y = fmaf(wv.y, sv.y, acc[i].y);
        }
    }
#pragma unroll
    for (int i = 0; i < 8; i++) {
        float a = acc[i].x + acc[i].y;
#pragma unroll
        for (int off = 16; off; off >>= 1)
            a += __shfl_xor_sync(0xffffffffu, a, off);
        if (lane == 0) out_logits[(n0 + i) * NC + c] = a;
    }
}

// ---------------------------------------------------------------------------
extern "C" void kernel_launch(void* const* d_in, const int* in_sizes, int n_in,
                              void* d_out, int out_size) {
    const float* F = (const float*)d_in[0];
    const float* P = (const float*)d_in[1];
    const float* W = (const float*)d_in[2];

    float* logits = (float*)d_out;           // [64,200]
    float* mind   = logits + NB * NC;        // [64,2000]

    // idempotent non-stream host APIs: capture-safe
    cudaFuncSetAttribute(proto_main_kernel,
                         cudaFuncAttributeMaxDynamicSharedMemorySize, SMEM_MAIN);
    cudaFuncSetAttribute(logits_kernel,
                         cudaFuncAttributeMaxDynamicSharedMemorySize, SMEM_LOGITS);

    xsq_kernel<<<NB, 256>>>(F);
    psq_kernel<<<(NP + 7) / 8, 256>>>(P);
    proto_main_kernel<<<dim3(PT_TILES, NB), 512, SMEM_MAIN>>>(F, P, mind);
    logits_kernel<<<dim3(NC / 8, NB / 8), 256, SMEM_LOGITS>>>(W, logits);
}

// round 8
// speedup vs baseline: 1.5304x; 1.0061x over previous
#include <cuda_runtime.h>
#include <cuda_bf16.h>
#include <cstdint>

// ---------------------------------------------------------------------------
// ProtoPNet fused kernel, GB300 sm_103a  (Round 8)
//   features   [64,128,14,14] f32   d_in[0]
//   prototypes [2000,128,1,1] f32   d_in[1]
//   last_weight[200,2000]     f32   d_in[2]
//   out: logits [64,200] then min_dist [64,2000]  (140800 f32)
//
// sim = log((d+1)/(d+eps)) strictly decreasing, relu monotone =>
// only min_hw(x_sq - 2*xp) per (n,p) is needed; one log per (n,p).
// Main GEMM: packed fp32 FFMA2 (fma.rn.f32x2).
// R8: warp = (proto-group x hw-half) -> feature smem traffic halved,
//     FMA pipe cleanly binding.
// ---------------------------------------------------------------------------

typedef unsigned long long ull;

#define NB   64       // batch
#define DD   128      // feature dim (K)
#define HW   196      // 14*14
#define HWP  256      // padded hw (128 f32x2 pairs)
#define NPAIR_VALID 98
#define NP   2000     // prototypes
#define TP   128      // prototypes per CTA
#define PT_TILES 16   // ceil(2000/128)
#define EPSV 1e-4f
#define NC   200      // classes

#define XSQ_STRIDE 200   // pad 196 -> 200 (8B-aligned float2)

__device__ float g_psq[NP];
__device__ float g_xsq[NB * XSQ_STRIDE];
__device__ float g_sim[NB * NP];

// ---- packed f32x2 helpers (Blackwell) -------------------------------------
__device__ __forceinline__ ull splat2(float v) {
    ull r;
    asm("mov.b64 %0, {%1, %1};" : "=l"(r) : "f"(v));
    return r;
}
__device__ __forceinline__ void fma2(ull& d, ull a, ull b) {
    asm("fma.rn.f32x2 %0, %1, %2, %3;" : "=l"(d) : "l"(a), "l"(b), "l"(d));
}
__device__ __forceinline__ float2 unpack2(ull v) {
    float2 r;
    asm("mov.b64 {%0, %1}, %2;" : "=f"(r.x), "=f"(r.y) : "l"(v));
    return r;
}

// ---- x_sq[n][hw] ----------------------------------------------------------
__global__ void xsq_kernel(const float* __restrict__ F) {
    int n  = blockIdx.x;
    int hw = threadIdx.x;
    if (hw < HW) {
        const float* base = F + (size_t)n * DD * HW + hw;
        float s = 0.f;
#pragma unroll 8
        for (int k = 0; k < DD; k++) {
            float v = base[(size_t)k * HW];
            s = fmaf(v, v, s);
        }
        g_xsq[n * XSQ_STRIDE + hw] = s;
    }
}

// ---- p_sq[p] (one warp per prototype) -------------------------------------
__global__ void psq_kernel(const float* __restrict__ P) {
    int w    = (blockIdx.x * blockDim.x + threadIdx.x) >> 5;
    int lane = threadIdx.x & 31;
    if (w < NP) {
        const float* row = P + (size_t)w * DD;
        float s = 0.f;
#pragma unroll
        for (int i = 0; i < 4; i++) {
            float v = row[lane + 32 * i];
            s = fmaf(v, v, s);
        }
#pragma unroll
        for (int off = 16; off; off >>= 1)
            s += __shfl_xor_sync(0xffffffffu, s, off);
        if (lane == 0) g_psq[w] = s;
    }
}

// ---- main fused GEMM + hw-min ---------------------------------------------
// grid (PT_TILES, NB), 512 threads = 16 warps.
// warp -> (pg = proto group of 16, jh = hw half of 64 pairs)
// smem: feat [128][256] (131072 B) + proto [128][128] (65536 B) = 196608 B dyn
#define SMEM_MAIN ((DD * HWP + TP * DD) * 4)

__global__ __launch_bounds__(512, 1)
void proto_main_kernel(const float* __restrict__ F,
                       const float* __restrict__ P,
                       float* __restrict__ out_mind) {
    extern __shared__ float sm[];
    float* sf = sm;                // feat  [128][256]
    float* sp = sm + DD * HWP;     // proto [128][128]
    __shared__ float smin[TP][2];  // per-(proto, hw-half) partial mins

    const int tid = threadIdx.x;
    const int tx  = tid & 31;      // lane
    const int ty  = tid >> 5;      // warp 0..15
    const int pg  = ty >> 1;       // proto group 0..7  (16 protos each)
    const int jh  = ty & 1;        // hw half: pairs [64*jh, 64*jh+64)
    const int n   = blockIdx.y;
    const int p0  = blockIdx.x * TP;

    // stage features (coalesced) + zero-pad hw 196..255
    const float* Fn = F + (size_t)n * DD * HW;
    for (int idx = tid; idx < DD * HW; idx += 512) {
        int k  = idx / HW;
        int hw = idx - k * HW;
        sf[k * HWP + hw] = Fn[idx];
    }
    for (int idx = tid; idx < DD * (HWP - HW); idx += 512) {
        int k  = idx / (HWP - HW);
        int hw = HW + (idx - k * (HWP - HW));
        sf[k * HWP + hw] = 0.f;
    }
    // stage prototypes, zero beyond NP
    for (int idx = tid; idx < TP * DD; idx += 512) {
        int pl = idx >> 7;
        int k  = idx & 127;
        int gp = p0 + pl;
        sp[idx] = (gp < NP) ? P[(size_t)gp * DD + k] : 0.f;
    }
    __syncthreads();

    // accumulators: 16 protos x 2 hw-pairs (this warp's half)
    ull acc[16][2];
#pragma unroll
    for (int i = 0; i < 16; i++) { acc[i][0] = 0ull; acc[i][1] = 0ull; }

    const ull*   f2  = reinterpret_cast<const ull*>(sf);   // [128][128] pairs
    const float* myp = sp + (pg * 16) * DD;
    const int    jb  = tx + 64 * jh;                        // pair index base

#pragma unroll 2
    for (int k = 0; k < DD; k += 2) {
        ull fa0 = f2[(k    ) * (HWP / 2) + jb];
        ull fa1 = f2[(k    ) * (HWP / 2) + jb + 32];
        ull fb0 = f2[(k + 1) * (HWP / 2) + jb];
        ull fb1 = f2[(k + 1) * (HWP / 2) + jb + 32];
#pragma unroll
        for (int i = 0; i < 16; i++) {
            float2 pv = *reinterpret_cast<const float2*>(myp + i * DD + k);
            ull b0 = splat2(pv.x);
            ull b1 = splat2(pv.y);
            fma2(acc[i][0], fa0, b0);
            fma2(acc[i][1], fa1, b0);
            fma2(acc[i][0], fb0, b1);
            fma2(acc[i][1], fb1, b1);
        }
    }

    // epilogue: per-warp min over its 64 pairs of (x_sq - 2*xp)
    const float2* xq = reinterpret_cast<const float2*>(g_xsq + n * XSQ_STRIDE);
    const int pi0 = jb;            // always < 98 (jh=1 -> 64..95)
    const int pi1 = jb + 32;       // may be >= 98
    float2 xs0 = xq[pi0];
    float2 xs1 = make_float2(0.f, 0.f);
    const bool v1 = (pi1 < NPAIR_VALID);
    if (v1) xs1 = xq[pi1];

#pragma unroll
    for (int i = 0; i < 16; i++) {
        float2 a0 = unpack2(acc[i][0]);
        float m = fminf(fmaf(-2.f, a0.x, xs0.x), fmaf(-2.f, a0.y, xs0.y));
        if (v1) {
            float2 a1 = unpack2(acc[i][1]);
            m = fminf(m, fmaf(-2.f, a1.x, xs1.x));
            m = fminf(m, fmaf(-2.f, a1.y, xs1.y));
        }
#pragma unroll
        for (int off = 16; off; off >>= 1)
            m = fminf(m, __shfl_xor_sync(0xffffffffu, m, off));
        if (tx == 0) smin[pg * 16 + i][jh] = m;
    }
    __syncthreads();

    // combine halves, add p_sq, relu, one log per (n,p)
    if (tid < TP) {
        int p = p0 + tid;
        if (p < NP) {
            float m  = fminf(smin[tid][0], smin[tid][1]);
            float md = fmaxf(m + g_psq[p], 0.f);
            out_mind[n * NP + p] = md;
            g_sim[n * NP + p]    = logf((md + 1.0f) / (md + EPSV));
        }
    }
}

// ---- logits: tiled GEMM  logits[n][c] = sum_p sim[n][p] * W[c][p] ---------
// grid (25 c-tiles, 8 n-tiles), 256 threads (8 warps = 8 classes/CTA).
#define SMEM_LOGITS (8 * NP * 4)

__global__ __launch_bounds__(256, 1)
void logits_kernel(const float* __restrict__ W,
                   float* __restrict__ out_logits) {
    extern __shared__ float s[];           // [8][2000]
    const int tid  = threadIdx.x;
    const int lane = tid & 31;
    const int w    = tid >> 5;             // warp -> class within tile
    const int c    = blockIdx.x * 8 + w;
    const int n0   = blockIdx.y * 8;

    for (int idx = tid; idx < 8 * NP; idx += 256) {
        int ni = idx / NP;
        int p  = idx - ni * NP;
        s[idx] = g_sim[(n0 + ni) * NP + p];
    }
    __syncthreads();

    const float2* wr = reinterpret_cast<const float2*>(W + (size_t)c * NP);
    const float2* s0 = reinterpret_cast<const float2*>(s);   // [8][1000] pairs
    float2 acc[8];
#pragma unroll
    for (int i = 0; i < 8; i++) acc[i] = make_float2(0.f, 0.f);

    for (int j = lane; j < NP / 2; j += 32) {
        float2 wv = wr[j];
#pragma unroll
        for (int i = 0; i < 8; i++) {
            float2 sv = s0[i * (NP / 2) + j];
            acc[i].x = fmaf(wv.x, sv.x, acc[i].x);
            acc[i].y = fmaf(wv.y, sv.y, acc[i].y);
        }
    }
#pragma unroll
    for (int i = 0; i < 8; i++) {
        float a = acc[i].x + acc[i].y;
#pragma unroll
        for (int off = 16; off; off >>= 1)
            a += __shfl_xor_sync(0xffffffffu, a, off);
        if (lane == 0) out_logits[(n0 + i) * NC + c] = a;
    }
}

// ---------------------------------------------------------------------------
extern "C" void kernel_launch(void* const* d_in, const int* in_sizes, int n_in,
                              void* d_out, int out_size) {
    const float* F = (const float*)d_in[0];
    const float* P = (const float*)d_in[1];
    const float* W = (const float*)d_in[2];

    float* logits = (float*)d_out;           // [64,200]
    float* mind   = logits + NB * NC;        // [64,2000]

    // idempotent non-stream host APIs: capture-safe
    cudaFuncSetAttribute(proto_main_kernel,
                         cudaFuncAttributeMaxDynamicSharedMemorySize, SMEM_MAIN);
    cudaFuncSetAttribute(logits_kernel,
                         cudaFuncAttributeMaxDynamicSharedMemorySize, SMEM_LOGITS);

    xsq_kernel<<<NB, 256>>>(F);
    psq_kernel<<<(NP + 7) / 8, 256>>>(P);
    proto_main_kernel<<<dim3(PT_TILES, NB), 512, SMEM_MAIN>>>(F, P, mind);
    logits_kernel<<<dim3(NC / 8, NB / 8), 256, SMEM_LOGITS>>>(W, logits);
}

// round 10
// speedup vs baseline: 3.1923x; 2.0859x over previous
#include <cuda_runtime.h>
#include <cuda_bf16.h>
#include <cstdint>

// ---------------------------------------------------------------------------
// ProtoPNet, GB300 sm_103a  (Round 10: tf32 mma.sync einsum)
//   features   [64,128,14,14] f32   d_in[0]
//   prototypes [2000,128,1,1] f32   d_in[1]
//   last_weight[200,2000]     f32   d_in[2]
//   out: logits [64,200] then min_dist [64,2000]
//
// NOTE: harness PTX target is compute_103 (no 'a') -> tcgen05 unavailable.
// Tensor path via baseline mma.sync.m16n8k8 tf32 (HMMA), fragment-prepacked.
//
// sim = log((d+1)/(d+eps)) strictly decreasing, relu monotone =>
// only min_hw(x_sq - 2*xp) per (n,p) needed; one log per (n,p).
// ---------------------------------------------------------------------------

#define NB    64
#define DD    128      // K
#define HW    196
#define NHW   224      // padded hw (28 x n8)
#define NP    2000
#define NPPAD 2048
#define EPSV  1e-4f
#define NC    200

#define MB_T  8        // m16 blocks per CTA  -> M = 128
#define NB_T  28       // n8 blocks per CTA   -> N = 224
#define KB_T  16       // k8 blocks           -> K = 128
#define MTILE 128
#define PT_TILES 16    // 2048/128

// packed fragment arrays
__device__ float g_pa[(NPPAD/16) * KB_T * 32 * 4];           // A frags (tf32 bits)
__device__ float g_pb[NB * NB_T * KB_T * 32 * 2];            // B frags (tf32 bits)
__device__ float g_psq[NP];
__device__ float g_xsq[NB * NHW];
__device__ float g_sim[NB * NP];

// smem layout (dynamic)
#define SM_XSQ  0                       // 224 f32 -> 896 B (round 1024)
#define SM_A    1024                    // 8*16*32*4*4  = 65536 B
#define SM_B    (SM_A + MB_T*KB_T*32*4*4)
#define SMEM_MAIN (SM_B + NB_T*KB_T*32*2*4)   // 1024+65536+114688 = 181248

__device__ __forceinline__ uint32_t to_tf32(float v) {
    uint32_t u;
    asm("cvt.rna.tf32.f32 %0, %1;" : "=r"(u) : "f"(v));
    return u;
}

__device__ __forceinline__ void mma8(float* d, uint4 a, uint2 b) {
    asm("mma.sync.aligned.m16n8k8.row.col.f32.tf32.tf32.f32 "
        "{%0,%1,%2,%3}, {%4,%5,%6,%7}, {%8,%9}, {%0,%1,%2,%3};"
        : "+f"(d[0]), "+f"(d[1]), "+f"(d[2]), "+f"(d[3])
        : "r"(a.x), "r"(a.y), "r"(a.z), "r"(a.w), "r"(b.x), "r"(b.y));
}

// ---- prep: pack protos into A-fragment order (tf32) -----------------------
// g_pa[mb][kb][lane][q]; q0:(g,t) q1:(g+8,t) q2:(g,t+4) q3:(g+8,t+4)
__global__ void prep_protos(const float* __restrict__ P) {
    int idx = blockIdx.x * blockDim.x + threadIdx.x;
    if (idx < (NPPAD/16) * KB_T * 32 * 4) {
        int q  = idx & 3;
        int l  = (idx >> 2) & 31;
        int kb = (idx >> 7) & (KB_T - 1);
        int mb = idx >> 11;
        int row = mb * 16 + (l >> 2) + 8 * (q & 1);
        int col = kb * 8 + (l & 3) + 4 * (q >> 1);
        float v = (row < NP) ? P[row * DD + col] : 0.f;
        g_pa[idx] = __uint_as_float(to_tf32(v));
    }
}

// ---- prep: pack features^T into B-fragment order (tf32) -------------------
// g_pb[n][nb][kb][lane][q]; q: k = kb*8 + t + 4q, hw = nb*8 + g
__global__ void prep_feat(const float* __restrict__ F) {
    int n = blockIdx.x;
    float* out = g_pb + (size_t)n * NB_T * KB_T * 32 * 2;
    const float* Fn = F + (size_t)n * DD * HW;
    for (int idx = threadIdx.x; idx < NB_T * KB_T * 32 * 2; idx += blockDim.x) {
        int q  = idx & 1;
        int l  = (idx >> 1) & 31;
        int kb = (idx >> 6) & (KB_T - 1);
        int nb = idx >> 10;
        int d  = kb * 8 + (l & 3) + 4 * q;
        int hw = nb * 8 + (l >> 2);
        float v = (hw < HW) ? Fn[d * HW + hw] : 0.f;
        out[idx] = __uint_as_float(to_tf32(v));
    }
}

// ---- x_sq[n][hw], pad -> huge so padded cols never win the min ------------
__global__ void xsq_kernel(const float* __restrict__ F) {
    int n  = blockIdx.x;
    int hw = threadIdx.x;
    if (hw < NHW) {
        float s = 1e30f;
        if (hw < HW) {
            const float* base = F + (size_t)n * DD * HW + hw;
            s = 0.f;
#pragma unroll 8
            for (int k = 0; k < DD; k++) {
                float v = base[(size_t)k * HW];
                s = fmaf(v, v, s);
            }
        }
        g_xsq[n * NHW + hw] = s;
    }
}

// ---- p_sq[p] (fp32 exact) -------------------------------------------------
__global__ void psq_kernel(const float* __restrict__ P) {
    int w    = (blockIdx.x * blockDim.x + threadIdx.x) >> 5;
    int lane = threadIdx.x & 31;
    if (w < NP) {
        const float* row = P + (size_t)w * DD;
        float s = 0.f;
#pragma unroll
        for (int i = 0; i < 4; i++) {
            float v = row[lane + 32 * i];
            s = fmaf(v, v, s);
        }
#pragma unroll
        for (int off = 16; off; off >>= 1)
            s += __shfl_xor_sync(0xffffffffu, s, off);
        if (lane == 0) g_psq[w] = s;
    }
}

// ---- main: tf32 HMMA einsum + fused min/sim epilogue ----------------------
// grid (16 proto-tiles, 64 n), 256 thr = 8 warps.
// warp = (wm = wid&1 -> m64) x (wn = wid>>1 -> n56). CTA tile 128 x 224 x 128.
__global__ __launch_bounds__(256, 1)
void proto_mma_kernel(float* __restrict__ out_mind) {
    extern __shared__ char smc[];
    float* xsq_s = reinterpret_cast<float*>(smc + SM_XSQ);
    __shared__ float smin[MTILE][4];

    const int tid  = threadIdx.x;
    const int lane = tid & 31;
    const int wid  = tid >> 5;
    const int wm   = wid & 1;
    const int wn   = wid >> 1;
    const int n    = blockIdx.y;
    const int p0   = blockIdx.x * MTILE;

    // stage packed tiles (pure linear copies, coalesced)
    {
        const uint4* gA = reinterpret_cast<const uint4*>(
            g_pa + (size_t)blockIdx.x * MB_T * KB_T * 32 * 4);
        uint4* sA = reinterpret_cast<uint4*>(smc + SM_A);
        for (int u = tid; u < MB_T * KB_T * 32; u += 256) sA[u] = gA[u];

        const uint4* gB = reinterpret_cast<const uint4*>(
            g_pb + (size_t)n * NB_T * KB_T * 32 * 2);
        uint4* sB = reinterpret_cast<uint4*>(smc + SM_B);
        for (int u = tid; u < NB_T * KB_T * 32 / 2; u += 256) sB[u] = gB[u];

        for (int i = tid; i < NHW; i += 256) xsq_s[i] = g_xsq[n * NHW + i];
    }
    __syncthreads();

    float d[4][7][4];
#pragma unroll
    for (int i = 0; i < 4; i++)
#pragma unroll
        for (int j = 0; j < 7; j++)
#pragma unroll
            for (int q = 0; q < 4; q++) d[i][j][q] = 0.f;

    const uint4* sA4 = reinterpret_cast<const uint4*>(smc + SM_A);
    const uint2* sB2 = reinterpret_cast<const uint2*>(smc + SM_B);

#pragma unroll 2
    for (int k = 0; k < KB_T; k++) {
        uint4 av[4];
#pragma unroll
        for (int i = 0; i < 4; i++)
            av[i] = sA4[((wm * 4 + i) * KB_T + k) * 32 + lane];
        uint2 bv[7];
#pragma unroll
        for (int j = 0; j < 7; j++)
            bv[j] = sB2[((wn * 7 + j) * KB_T + k) * 32 + lane];
#pragma unroll
        for (int i = 0; i < 4; i++)
#pragma unroll
            for (int j = 0; j < 7; j++)
                mma8(d[i][j], av[i], bv[j]);
    }

    // epilogue: min over this warp's 56 cols of (xsq - 2*xp)
    const int g = lane >> 2, t = lane & 3;
#pragma unroll
    for (int i = 0; i < 4; i++) {
        float mA = 1e30f, mB = 1e30f;
#pragma unroll
        for (int j = 0; j < 7; j++) {
            int col = wn * 56 + j * 8 + 2 * t;
            float xs0 = xsq_s[col], xs1 = xsq_s[col + 1];
            mA = fminf(mA, fminf(fmaf(-2.f, d[i][j][0], xs0),
                                 fmaf(-2.f, d[i][j][1], xs1)));
            mB = fminf(mB, fminf(fmaf(-2.f, d[i][j][2], xs0),
                                 fmaf(-2.f, d[i][j][3], xs1)));
        }
        // reduce over the 4 lanes of each row-group (t = 0..3)
        mA = fminf(mA, __shfl_xor_sync(0xffffffffu, mA, 1));
        mA = fminf(mA, __shfl_xor_sync(0xffffffffu, mA, 2));
        mB = fminf(mB, __shfl_xor_sync(0xffffffffu, mB, 1));
        mB = fminf(mB, __shfl_xor_sync(0xffffffffu, mB, 2));
        if (t == 0) {
            smin[wm * 64 + i * 16 + g    ][wn] = mA;
            smin[wm * 64 + i * 16 + g + 8][wn] = mB;
        }
    }
    __syncthreads();

    if (tid < MTILE) {
        int p = p0 + tid;
        if (p < NP) {
            float m = fminf(fminf(smin[tid][0], smin[tid][1]),
                            fminf(smin[tid][2], smin[tid][3]));
            float md = fmaxf(m + g_psq[p], 0.f);
            out_mind[n * NP + p] = md;
            g_sim[n * NP + p]    = logf((md + 1.0f) / (md + EPSV));
        }
    }
}

// ---- logits: tiled GEMM, grid (25 c-tiles, 16 n-tiles of 4) ---------------
#define SMEM_LOGITS (4 * NP * 4)

__global__ __launch_bounds__(256, 1)
void logits_kernel(const float* __restrict__ W,
                   float* __restrict__ out_logits) {
    extern __shared__ float s[];           // [4][2000]
    const int tid  = threadIdx.x;
    const int lane = tid & 31;
    const int w    = tid >> 5;
    const int c    = blockIdx.x * 8 + w;
    const int n0   = blockIdx.y * 4;

    for (int idx = tid; idx < 4 * NP; idx += 256) {
        int ni = idx / NP;
        int p  = idx - ni * NP;
        s[idx] = g_sim[(n0 + ni) * NP + p];
    }
    __syncthreads();

    const float2* wr = reinterpret_cast<const float2*>(W + (size_t)c * NP);
    const float2* s0 = reinterpret_cast<const float2*>(s);
    float2 acc[4];
#pragma unroll
    for (int i = 0; i < 4; i++) acc[i] = make_float2(0.f, 0.f);

    for (int j = lane; j < NP / 2; j += 32) {
        float2 wv = wr[j];
#pragma unroll
        for (int i = 0; i < 4; i++) {
            float2 sv = s0[i * (NP / 2) + j];
            acc[i].x = fmaf(wv.x, sv.x, acc[i].x);
            acc[i].y = fmaf(wv.y, sv.y, acc[i].y);
        }
    }
#pragma unroll
    for (int i = 0; i < 4; i++) {
        float a = acc[i].x + acc[i].y;
#pragma unroll
        for (int off = 16; off; off >>= 1)
            a += __shfl_xor_sync(0xffffffffu, a, off);
        if (lane == 0) out_logits[(n0 + i) * NC + c] = a;
    }
}

// ---------------------------------------------------------------------------
extern "C" void kernel_launch(void* const* d_in, const int* in_sizes, int n_in,
                              void* d_out, int out_size) {
    const float* F = (const float*)d_in[0];
    const float* P = (const float*)d_in[1];
    const float* W = (const float*)d_in[2];

    float* logits = (float*)d_out;           // [64,200]
    float* mind   = logits + NB * NC;        // [64,2000]

    cudaFuncSetAttribute(proto_mma_kernel,
                         cudaFuncAttributeMaxDynamicSharedMemorySize, SMEM_MAIN);
    cudaFuncSetAttribute(logits_kernel,
                         cudaFuncAttributeMaxDynamicSharedMemorySize, SMEM_LOGITS);

    prep_protos<<<((NPPAD/16)*KB_T*32*4 + 255) / 256, 256>>>(P);
    prep_feat<<<NB, 256>>>(F);
    xsq_kernel<<<NB, NHW>>>(F);
    psq_kernel<<<(NP + 7) / 8, 256>>>(P);
    proto_mma_kernel<<<dim3(PT_TILES, NB), 256, SMEM_MAIN>>>(mind);
    logits_kernel<<<dim3(NC / 8, NB / 4), 256, SMEM_LOGITS>>>(W, logits);
}

// round 12
// speedup vs baseline: 4.0263x; 1.2613x over previous
#include <cuda_runtime.h>
#include <cuda_bf16.h>
#include <cstdint>

// ---------------------------------------------------------------------------
// ProtoPNet, GB300 sm_103a  (Round 12 = Round 11 re-bench after infra flake)
//   features   [64,128,14,14] f32   d_in[0]
//   prototypes [2000,128,1,1] f32   d_in[1]
//   last_weight[200,2000]     f32   d_in[2]
//   out: logits [64,200] then min_dist [64,2000]
//
// compute_103 target -> no tcgen05; tensor path via mma.sync m16n8k8 tf32.
// sim = log((d+1)/(d+eps)) strictly decreasing, relu monotone =>
// only min_hw(x_sq - 2*xp) per (n,p) needed; one log per (n,p).
//
// Single wave: grid 128 CTAs (2 proto-halves x 64 n). B tile staged once,
// A fragments streamed from L2 with register prefetch. Prep kernels
// read-coalesced / write-scattered.
// ---------------------------------------------------------------------------

#define NB    64
#define DD    128      // K
#define HW    196
#define NHW   224      // padded hw (28 x n8)
#define NP    2000
#define NPPAD 2048
#define EPSV  1e-4f
#define NC    200

#define KB_T  16       // k8 blocks -> K = 128
#define NB_T  28       // n8 blocks -> N = 224
#define MTILE 128      // protos per tile (8 x m16)
#define TPC   8        // tiles per CTA (half = 1024 protos)

// packed fragment arrays (zero-initialized device globals; padding never written)
__device__ float g_pa[(NPPAD/16) * KB_T * 32 * 4];   // A frags [mb][kb][lane][4]
__device__ float g_pb[NB * NB_T * KB_T * 32 * 2];    // B frags [n][nb][kb][lane][2]
__device__ float g_psq[NP];
__device__ float g_xsq[NB * NHW];
__device__ float g_sim[NB * NP];

// main-kernel smem
#define SM_XSQ  0
#define SM_B    1024
#define SMEM_MAIN (SM_B + NB_T * KB_T * 32 * 2 * 4)   // 1024 + 114688 = 115712

__device__ __forceinline__ uint32_t to_tf32(float v) {
    uint32_t u;
    asm("cvt.rna.tf32.f32 %0, %1;" : "=r"(u) : "f"(v));
    return u;
}

__device__ __forceinline__ void mma8(float* d, uint4 a, uint2 b) {
    asm("mma.sync.aligned.m16n8k8.row.col.f32.tf32.tf32.f32 "
        "{%0,%1,%2,%3}, {%4,%5,%6,%7}, {%8,%9}, {%0,%1,%2,%3};"
        : "+f"(d[0]), "+f"(d[1]), "+f"(d[2]), "+f"(d[3])
        : "r"(a.x), "r"(a.y), "r"(a.z), "r"(a.w), "r"(b.x), "r"(b.y));
}

// ---- prep: pack protos into A-fragment order (coalesced reads) ------------
// A frag: row = mb*16 + (l>>2) + 8*(q&1), col = kb*8 + (l&3) + 4*(q>>1)
__global__ void prep_protos(const float* __restrict__ P) {
    int idx = blockIdx.x * blockDim.x + threadIdx.x;   // linear over P
    if (idx < NP * DD) {
        int row = idx >> 7, col = idx & 127;
        int mb = row >> 4, rr = row & 15;
        int kb = col >> 3, cc = col & 7;
        int q  = (rr >> 3) + 2 * (cc >> 2);
        int l  = (rr & 7) * 4 + (cc & 3);
        g_pa[((mb * KB_T + kb) * 32 + l) * 4 + q] =
            __uint_as_float(to_tf32(P[idx]));
    }
}

// ---- prep: pack features^T into B-fragment order (coalesced reads) --------
// B frag: d = kb*8 + (l&3) + 4*q, hw = nb*8 + (l>>2)
__global__ void prep_feat(const float* __restrict__ F) {
    int n = blockIdx.x;
    const float* Fn = F + (size_t)n * DD * HW;
    float* out = g_pb + (size_t)n * NB_T * KB_T * 64;
    for (int idx = threadIdx.x; idx < DD * HW; idx += blockDim.x) {
        int d  = idx / HW;
        int hw = idx - d * HW;
        int nb = hw >> 3, g = hw & 7;
        int kb = d >> 3,  r = d & 7;
        out[((nb * KB_T + kb) * 32 + g * 4 + (r & 3)) * 2 + (r >> 2)] =
            __uint_as_float(to_tf32(Fn[idx]));
    }
}

// ---- x_sq[n][hw], pad -> huge so padded cols never win the min ------------
__global__ void xsq_kernel(const float* __restrict__ F) {
    int n  = blockIdx.x;
    int hw = threadIdx.x;
    if (hw < NHW) {
        float s = 1e30f;
        if (hw < HW) {
            const float* base = F + (size_t)n * DD * HW + hw;
            s = 0.f;
#pragma unroll 8
            for (int k = 0; k < DD; k++) {
                float v = base[(size_t)k * HW];
                s = fmaf(v, v, s);
            }
        }
        g_xsq[n * NHW + hw] = s;
    }
}

// ---- p_sq[p] (fp32 exact) -------------------------------------------------
__global__ void psq_kernel(const float* __restrict__ P) {
    int w    = (blockIdx.x * blockDim.x + threadIdx.x) >> 5;
    int lane = threadIdx.x & 31;
    if (w < NP) {
        const float* row = P + (size_t)w * DD;
        float s = 0.f;
#pragma unroll
        for (int i = 0; i < 4; i++) {
            float v = row[lane + 32 * i];
            s = fmaf(v, v, s);
        }
#pragma unroll
        for (int off = 16; off; off >>= 1)
            s += __shfl_xor_sync(0xffffffffu, s, off);
        if (lane == 0) g_psq[w] = s;
    }
}

// ---- main: single-wave tf32 HMMA einsum + fused min/sim epilogue ----------
// grid (2 proto-halves, 64 n), 256 thr = 8 warps.
// warp = (wm = wid&1 -> m64) x (wn = wid>>1 -> n56).
// B tile (features, all 224 hw) staged once; 8 proto-tiles streamed from L2.
__global__ __launch_bounds__(256, 1)
void proto_mma_kernel(float* __restrict__ out_mind) {
    extern __shared__ char smc[];
    float* xsq_s = reinterpret_cast<float*>(smc + SM_XSQ);
    __shared__ float smin[MTILE][4];

    const int tid  = threadIdx.x;
    const int lane = tid & 31;
    const int wid  = tid >> 5;
    const int wm   = wid & 1;
    const int wn   = wid >> 1;
    const int n    = blockIdx.y;
    const int half = blockIdx.x;

    // stage B (coalesced linear copy) + xsq
    {
        const uint4* gB = reinterpret_cast<const uint4*>(
            g_pb + (size_t)n * NB_T * KB_T * 64);
        uint4* sB = reinterpret_cast<uint4*>(smc + SM_B);
        for (int u = tid; u < NB_T * KB_T * 16; u += 256) sB[u] = gB[u];
        for (int i = tid; i < NHW; i += 256) xsq_s[i] = g_xsq[n * NHW + i];
    }
    __syncthreads();

    const uint2* sB2 = reinterpret_cast<const uint2*>(smc + SM_B);
    const int g = lane >> 2, t4 = lane & 3;

    for (int t = 0; t < TPC; t++) {
        const int tt = half * TPC + t;                 // global tile 0..15
        const int p0 = tt * MTILE;
        const uint4* gA = reinterpret_cast<const uint4*>(g_pa)
                          + (size_t)tt * 8 * KB_T * 32;

        float d[4][7][4];
#pragma unroll
        for (int i = 0; i < 4; i++)
#pragma unroll
            for (int j = 0; j < 7; j++)
#pragma unroll
                for (int q = 0; q < 4; q++) d[i][j][q] = 0.f;

        uint4 avc[4], avn[4];
#pragma unroll
        for (int i = 0; i < 4; i++)
            avc[i] = gA[((wm * 4 + i) * KB_T) * 32 + lane];

#pragma unroll
        for (int k = 0; k < KB_T; k++) {
            const int kn = (k + 1 < KB_T) ? (k + 1) : k;   // tail: benign reload
#pragma unroll
            for (int i = 0; i < 4; i++)
                avn[i] = gA[((wm * 4 + i) * KB_T + kn) * 32 + lane];
            uint2 bv[7];
#pragma unroll
            for (int j = 0; j < 7; j++)
                bv[j] = sB2[((wn * 7 + j) * KB_T + k) * 32 + lane];
#pragma unroll
            for (int i = 0; i < 4; i++)
#pragma unroll
                for (int j = 0; j < 7; j++)
                    mma8(d[i][j], avc[i], bv[j]);
#pragma unroll
            for (int i = 0; i < 4; i++) avc[i] = avn[i];
        }

        // epilogue: min over this warp's 56 cols of (xsq - 2*xp)
#pragma unroll
        for (int i = 0; i < 4; i++) {
            float mA = 1e30f, mB = 1e30f;
#pragma unroll
            for (int j = 0; j < 7; j++) {
                int col = wn * 56 + j * 8 + 2 * t4;
                float xs0 = xsq_s[col], xs1 = xsq_s[col + 1];
                mA = fminf(mA, fminf(fmaf(-2.f, d[i][j][0], xs0),
                                     fmaf(-2.f, d[i][j][1], xs1)));
                mB = fminf(mB, fminf(fmaf(-2.f, d[i][j][2], xs0),
                                     fmaf(-2.f, d[i][j][3], xs1)));
            }
            mA = fminf(mA, __shfl_xor_sync(0xffffffffu, mA, 1));
            mA = fminf(mA, __shfl_xor_sync(0xffffffffu, mA, 2));
            mB = fminf(mB, __shfl_xor_sync(0xffffffffu, mB, 1));
            mB = fminf(mB, __shfl_xor_sync(0xffffffffu, mB, 2));
            if (t4 == 0) {
                smin[wm * 64 + i * 16 + g    ][wn] = mA;
                smin[wm * 64 + i * 16 + g + 8][wn] = mB;
            }
        }
        __syncthreads();

        if (tid < MTILE) {
            int p = p0 + tid;
            if (p < NP) {
                float m = fminf(fminf(smin[tid][0], smin[tid][1]),
                                fminf(smin[tid][2], smin[tid][3]));
                float md = fmaxf(m + g_psq[p], 0.f);
                out_mind[n * NP + p] = md;
                g_sim[n * NP + p]    = logf((md + 1.0f) / (md + EPSV));
            }
        }
        __syncthreads();   // smin reused next tile
    }
}

// ---- logits: tiled GEMM, grid (25 c-tiles, 16 n-tiles of 4) ---------------
#define SMEM_LOGITS (4 * NP * 4)

__global__ __launch_bounds__(256, 1)
void logits_kernel(const float* __restrict__ W,
                   float* __restrict__ out_logits) {
    extern __shared__ float s[];           // [4][2000]
    const int tid  = threadIdx.x;
    const int lane = tid & 31;
    const int w    = tid >> 5;
    const int c    = blockIdx.x * 8 + w;
    const int n0   = blockIdx.y * 4;

    for (int idx = tid; idx < 4 * NP; idx += 256) {
        int ni = idx / NP;
        int p  = idx - ni * NP;
        s[idx] = g_sim[(n0 + ni) * NP + p];
    }
    __syncthreads();

    const float2* wr = reinterpret_cast<const float2*>(W + (size_t)c * NP);
    const float2* s0 = reinterpret_cast<const float2*>(s);
    float2 acc[4];
#pragma unroll
    for (int i = 0; i < 4; i++) acc[i] = make_float2(0.f, 0.f);

    for (int j = lane; j < NP / 2; j += 32) {
        float2 wv = wr[j];
#pragma unroll
        for (int i = 0; i < 4; i++) {
            float2 sv = s0[i * (NP / 2) + j];
            acc[i].x = fmaf(wv.x, sv.x, acc[i].x);
            acc[i].y = fmaf(wv.y, sv.y, acc[i].y);
        }
    }
#pragma unroll
    for (int i = 0; i < 4; i++) {
        float a = acc[i].x + acc[i].y;
#pragma unroll
        for (int off = 16; off; off >>= 1)
            a += __shfl_xor_sync(0xffffffffu, a, off);
        if (lane == 0) out_logits[(n0 + i) * NC + c] = a;
    }
}

// ---------------------------------------------------------------------------
extern "C" void kernel_launch(void* const* d_in, const int* in_sizes, int n_in,
                              void* d_out, int out_size) {
    const float* F = (const float*)d_in[0];
    const float* P = (const float*)d_in[1];
    const float* W = (const float*)d_in[2];

    float* logits = (float*)d_out;           // [64,200]
    float* mind   = logits + NB * NC;        // [64,2000]

    cudaFuncSetAttribute(proto_mma_kernel,
                         cudaFuncAttributeMaxDynamicSharedMemorySize, SMEM_MAIN);
    cudaFuncSetAttribute(logits_kernel,
                         cudaFuncAttributeMaxDynamicSharedMemorySize, SMEM_LOGITS);

    prep_protos<<<(NP * DD + 255) / 256, 256>>>(P);
    prep_feat<<<NB, 256>>>(F);
    xsq_kernel<<<NB, NHW>>>(F);
    psq_kernel<<<(NP + 7) / 8, 256>>>(P);
    proto_mma_kernel<<<dim3(2, NB), 256, SMEM_MAIN>>>(mind);
    logits_kernel<<<dim3(NC / 8, NB / 4), 256, SMEM_LOGITS>>>(W, logits);
}